// round 8
// baseline (speedup 1.0000x reference)
#include <cuda_runtime.h>

// TemporalDecay: out = h + (1-m)*g*(h_fwd - h),
//   g = exp(-relu(delta*W + b)),  delta integer in [1,4],
//   h_fwd[b,t,j] = h_a[b, t-(delta-1), j]   (<= 3 rows back).
//
// R8: SEG=1 row per thread -> live set ~36 floats, so __launch_bounds__(128,10)
// (51-reg cap) fits without spilling: 10 blocks x 4 warps = 40 warps/SM
// (62.5% occ) vs R7's 36. Halo rows and the gamma table are L1/L2 hits; the
// extra L1 wavefronts (~10/row vs 7) stay below the L1 wall while the added
// warps push DRAM toward saturation. gamma table + PDL retained.

static constexpr int Bq = 32, Tq = 2048;
static constexpr int C4 = 64;          // float4s per 256-channel row
static constexpr int THREADS = 128;
static constexpr int NROWS = Bq * Tq;  // 65536 (b,t) rows
static constexpr int BLOCKS = NROWS * C4 / THREADS;  // 32768

// gamma[d-1][channel], 4 rows of 64 float4s (only rows 1..3 read by decay).
__device__ float4 g_gamma4[4 * C4];

__global__ void gamma_precompute_kernel(const float* __restrict__ W,
                                        const float* __restrict__ bias) {
    cudaTriggerProgrammaticLaunchCompletion();
    int j = threadIdx.x;  // 0..255 channel
    float w = W[j];
    float bb = bias[j];
    float* gf = (float*)g_gamma4;
#pragma unroll
    for (int dm = 0; dm < 4; dm++) {
        float x = fmaxf(fmaf((float)(dm + 1), w, bb), 0.0f);
        gf[dm * 256 + j] = __expf(-x);
    }
}

__global__ void __launch_bounds__(THREADS, 10) decay_kernel(
    const float4* __restrict__ H,      // h_a  [B*T*64] float4
    const float4* __restrict__ DL,     // deltas [B*T*16] float4
    const float4* __restrict__ MM,     // mask   [B*T*16] float4
    float4* __restrict__ OUT)
{
    const int g    = blockIdx.x * THREADS + threadIdx.x;
    const int col4 = g & 63;
    const int r    = g >> 6;           // (b,t) row: r = bb*Tq + t
    const int t    = r & (Tq - 1);

    const int hbase = r * C4 + col4;           // float4 index into H/OUT
    const int dq    = r * 16 + (col4 & 15);    // float4 index into DL/MM

    // --- gamma-independent loads first (overlap with gamma kernel via PDL) ---
    const float4 ha = __ldg(H + hbase);
    // halo rows t-1..t-3 (clamped; clamped values never selected since
    // reference guarantees delta <= t+1)
    const int m1 = (t >= 1) ? C4 : 0;
    const int m2 = (t >= 2) ? 2 * C4 : m1;
    const int m3 = (t >= 3) ? 3 * C4 : m2;
    const float4 w1 = __ldg(H + hbase - m1);
    const float4 w2 = __ldg(H + hbase - m2);
    const float4 w3 = __ldg(H + hbase - m3);

    const float4 dl = __ldg(DL + dq);
    const float4 mm = __ldg(MM + dq);

    // --- wait for gamma table, then load this thread's 3 float4s (L1-hot) ---
    cudaGridDependencySynchronize();
    const float4 gam1 = __ldg(g_gamma4 + 1 * C4 + col4);
    const float4 gam2 = __ldg(g_gamma4 + 2 * C4 + col4);
    const float4 gam3 = __ldg(g_gamma4 + 3 * C4 + col4);

    // --- compute + store (float-domain selects; delta in {1,2,3,4}) ---
    float4 o;
#define PROC(c)                                                       \
    {                                                                 \
        const float dv = dl.c;                                        \
        const float f  = (dv == 1.0f) ? ha.c                          \
                       : (dv == 2.0f) ? w1.c                          \
                       : (dv == 3.0f) ? w2.c : w3.c;                  \
        const float gv = (dv == 2.0f) ? gam1.c                        \
                       : (dv == 3.0f) ? gam2.c : gam3.c;              \
        /* dv==1 => f-ha==0, gv irrelevant */                         \
        o.c = fmaf((1.0f - mm.c) * gv, f - ha.c, ha.c);               \
    }
    PROC(x) PROC(y) PROC(z) PROC(w)
#undef PROC
    OUT[hbase] = o;
}

extern "C" void kernel_launch(void* const* d_in, const int* in_sizes, int n_in,
                              void* d_out, int out_size) {
    const float4* h_a    = (const float4*)d_in[0];
    const float4* deltas = (const float4*)d_in[1];
    const float4* Mmask  = (const float4*)d_in[2];
    const float*  W      = (const float*)d_in[3];
    const float*  b      = (const float*)d_in[4];
    float4* out = (float4*)d_out;

    gamma_precompute_kernel<<<1, 256>>>(W, b);

    // PDL: decay launches/overlaps while gamma runs; decay grid-dep-syncs
    // before touching the table.
    cudaLaunchAttribute attr[1];
    attr[0].id = cudaLaunchAttributeProgrammaticStreamSerialization;
    attr[0].val.programmaticStreamSerializationAllowed = 1;
    cudaLaunchConfig_t cfg = {};
    cfg.gridDim = dim3(BLOCKS);
    cfg.blockDim = dim3(THREADS);
    cfg.dynamicSmemBytes = 0;
    cfg.stream = 0;
    cfg.attrs = attr;
    cfg.numAttrs = 1;
    cudaLaunchKernelEx(&cfg, decay_kernel, h_a, deltas, Mmask, out);
}

// round 9
// speedup vs baseline: 1.1040x; 1.1040x over previous
#include <cuda_runtime.h>

// TemporalDecay: out = h + (1-m)*g*(h_fwd - h),
//   g = exp(-relu(delta*W + b)),  delta integer in [1,4],
//   h_fwd[b,t,j] = h_a[b, t-(delta-1), j]   (<= 3 rows back).
//
// R9: each thread does 4 consecutive t rows as TWO chunks of 2. Chunk 2's
// halo rows and gamma are already in registers from chunk 1, so chunk 2 pays
// only 2H+2DL+2MM+2STG -> 72 L1 wavefronts per 4 rows vs R7's 96. A compiler
// memory fence between chunk-1 stores and chunk-2 loads stops ptxas from
// hoisting (which would blow past the 64-reg cap and spill, as in R4).
// __launch_bounds__(128,8): 64-reg cap, 32 warps/SM. gamma table + PDL kept.

static constexpr int Bq = 32, Tq = 2048;
static constexpr int C4 = 64;           // float4s per 256-channel row
static constexpr int SEGT = 4;          // t rows per thread (2 chunks of 2)
static constexpr int NSEG = Tq / SEGT;  // 512
static constexpr int THREADS = 128;
static constexpr int BLOCKS = Bq * C4 * NSEG / THREADS;  // 8192

// gamma[d-1][channel], 4 rows of 64 float4s (only rows 1..3 read by decay).
__device__ float4 g_gamma4[4 * C4];

__global__ void gamma_precompute_kernel(const float* __restrict__ W,
                                        const float* __restrict__ bias) {
    cudaTriggerProgrammaticLaunchCompletion();
    int j = threadIdx.x;  // 0..255 channel
    float w = W[j];
    float bb = bias[j];
    float* gf = (float*)g_gamma4;
#pragma unroll
    for (int dm = 0; dm < 4; dm++) {
        float x = fmaxf(fmaf((float)(dm + 1), w, bb), 0.0f);
        gf[dm * 256 + j] = __expf(-x);
    }
}

// One output row: ha=row t, w1/w2/w3 = rows t-1..t-3, dl/mm row data.
__device__ __forceinline__ float4 proc_row(
    const float4 ha, const float4 w1, const float4 w2, const float4 w3,
    const float4 dl, const float4 mm,
    const float4 gam1, const float4 gam2, const float4 gam3)
{
    float4 o;
#define PROC(c)                                                       \
    {                                                                 \
        const float dv = dl.c;                                        \
        const float f  = (dv == 1.0f) ? ha.c                          \
                       : (dv == 2.0f) ? w1.c                          \
                       : (dv == 3.0f) ? w2.c : w3.c;                  \
        const float gv = (dv == 2.0f) ? gam1.c                        \
                       : (dv == 3.0f) ? gam2.c : gam3.c;              \
        /* dv==1 => f-ha==0, gv irrelevant */                         \
        o.c = fmaf((1.0f - mm.c) * gv, f - ha.c, ha.c);               \
    }
    PROC(x) PROC(y) PROC(z) PROC(w)
#undef PROC
    return o;
}

__global__ void __launch_bounds__(THREADS, 8) decay_kernel(
    const float4* __restrict__ H,      // h_a  [B*T*64] float4
    const float4* __restrict__ DL,     // deltas [B*T*16] float4
    const float4* __restrict__ MM,     // mask   [B*T*16] float4
    float4* __restrict__ OUT)
{
    const int g    = blockIdx.x * THREADS + threadIdx.x;
    const int col4 = g & 63;
    const int seg  = (g >> 6) & (NSEG - 1);
    const int bb   = g >> 15;
    const int t0   = seg * SEGT;

    const int rb    = bb * Tq * C4 + col4;              // row base into H/OUT
    const int dbase = (bb * Tq + t0) * 16 + (col4 & 15);

    // ---- chunk 1 loads (gamma-independent; overlap gamma kernel via PDL) ----
    const int tm1 = max(t0 - 1, 0), tm2 = max(t0 - 2, 0), tm3 = max(t0 - 3, 0);
    const float4 hm1 = __ldg(H + rb + tm1 * C4);   // row t0-1 (clamped)
    const float4 hm2 = __ldg(H + rb + tm2 * C4);   // row t0-2
    const float4 hm3 = __ldg(H + rb + tm3 * C4);   // row t0-3
    const float4 h0  = __ldg(H + rb + (t0 + 0) * C4);
    const float4 h1  = __ldg(H + rb + (t0 + 1) * C4);
    const float4 dl0 = __ldg(DL + dbase + 0 * 16);
    const float4 dl1 = __ldg(DL + dbase + 1 * 16);
    const float4 mm0 = __ldg(MM + dbase + 0 * 16);
    const float4 mm1 = __ldg(MM + dbase + 1 * 16);

    // ---- gamma table (L1-hot, loaded once per thread, reused both chunks) ----
    cudaGridDependencySynchronize();
    const float4 gam1 = __ldg(g_gamma4 + 1 * C4 + col4);
    const float4 gam2 = __ldg(g_gamma4 + 2 * C4 + col4);
    const float4 gam3 = __ldg(g_gamma4 + 3 * C4 + col4);

    // ---- chunk 1 compute + store ----
    OUT[rb + (t0 + 0) * C4] = proc_row(h0, hm1, hm2, hm3, dl0, mm0, gam1, gam2, gam3);
    OUT[rb + (t0 + 1) * C4] = proc_row(h1, h0, hm1, hm2, dl1, mm1, gam1, gam2, gam3);

    // Fence: keep chunk-2 loads below chunk-1 (limits live registers; the
    // chunk-2 DRAM latency is hidden by the 32 resident warps).
    asm volatile("" ::: "memory");

    // ---- chunk 2: halo (h1, h0, hm1) and gamma already in registers ----
    const float4 h2  = __ldg(H + rb + (t0 + 2) * C4);
    const float4 h3  = __ldg(H + rb + (t0 + 3) * C4);
    const float4 dl2 = __ldg(DL + dbase + 2 * 16);
    const float4 dl3 = __ldg(DL + dbase + 3 * 16);
    const float4 mm2 = __ldg(MM + dbase + 2 * 16);
    const float4 mm3 = __ldg(MM + dbase + 3 * 16);

    OUT[rb + (t0 + 2) * C4] = proc_row(h2, h1, h0, hm1, dl2, mm2, gam1, gam2, gam3);
    OUT[rb + (t0 + 3) * C4] = proc_row(h3, h2, h1, h0, dl3, mm3, gam1, gam2, gam3);
}

extern "C" void kernel_launch(void* const* d_in, const int* in_sizes, int n_in,
                              void* d_out, int out_size) {
    const float4* h_a    = (const float4*)d_in[0];
    const float4* deltas = (const float4*)d_in[1];
    const float4* Mmask  = (const float4*)d_in[2];
    const float*  W      = (const float*)d_in[3];
    const float*  b      = (const float*)d_in[4];
    float4* out = (float4*)d_out;

    gamma_precompute_kernel<<<1, 256>>>(W, b);

    // PDL: decay launches/overlaps while gamma runs; decay grid-dep-syncs
    // before touching the table.
    cudaLaunchAttribute attr[1];
    attr[0].id = cudaLaunchAttributeProgrammaticStreamSerialization;
    attr[0].val.programmaticStreamSerializationAllowed = 1;
    cudaLaunchConfig_t cfg = {};
    cfg.gridDim = dim3(BLOCKS);
    cfg.blockDim = dim3(THREADS);
    cfg.dynamicSmemBytes = 0;
    cfg.stream = 0;
    cfg.attrs = attr;
    cfg.numAttrs = 1;
    cudaLaunchKernelEx(&cfg, decay_kernel, h_a, deltas, Mmask, out);
}